// round 13
// baseline (speedup 1.0000x reference)
#include <cuda_runtime.h>
#include <cstdint>

// ---------------- problem constants (static shapes) ----------------
#define HEADS 6
#define LW    144
#define HD    32
#define CDIM  192
#define NW    64
#define WWINS 15
#define BTOT  960
#define M1    (BTOT*LW)      // 138240
#define N1    576
#define K1    192
#define TABNH (NW*HEADS)

// ---------------- scratch (device globals; no allocations) ----------------
__device__ float g_q[(size_t)BTOT*HEADS*LW*HD];
__device__ float g_k[(size_t)BTOT*HEADS*LW*HD];
__device__ float g_v[(size_t)BTOT*HEADS*LW*HD];   // stored TRANSPOSED: [w][h][d][l]
__device__ float g_att[(size_t)BTOT*LW*CDIM];     // tf32-rounded by k_attn
__device__ float g_w1r[(size_t)K1*N1];            // tf32-rounded W1 [k][n]
__device__ float g_w2r[(size_t)CDIM*CDIM];        // tf32-rounded W2 [k][n]
// quad-fragment-ordered bias/mask: [group][mt(9)][cb(2)][nt(9)][lane(32)][4]
__device__ float g_biasQ[(size_t)NW*HEADS*9*2*9*32*4];
__device__ float g_maskQ[(size_t)BTOT*9*2*9*32*4];

// ---------------- helpers ----------------
__device__ __forceinline__ float tf32r(float x) {
    unsigned int u;
    asm("cvt.rna.tf32.f32 %0, %1;" : "=r"(u) : "f"(x));
    return __uint_as_float(u);
}
__device__ __forceinline__ unsigned tf32u(unsigned v) {
    unsigned o;
    asm("cvt.rna.tf32.f32 %0, %1;" : "=r"(o) : "f"(__uint_as_float(v)));
    return o;
}
__device__ __forceinline__ float4 tf32r4(float4 v) {
    float4 t;
    t.x = tf32r(v.x); t.y = tf32r(v.y); t.z = tf32r(v.z); t.w = tf32r(v.w);
    return t;
}

__device__ __forceinline__ void mma8(float c[4],
                                     unsigned a0, unsigned a1, unsigned a2, unsigned a3,
                                     unsigned b0, unsigned b1) {
    asm volatile(
        "mma.sync.aligned.m16n8k8.row.col.f32.tf32.tf32.f32 "
        "{%0,%1,%2,%3}, {%4,%5,%6,%7}, {%8,%9}, {%0,%1,%2,%3};\n"
        : "+f"(c[0]), "+f"(c[1]), "+f"(c[2]), "+f"(c[3])
        : "r"(a0), "r"(a1), "r"(a2), "r"(a3), "r"(b0), "r"(b1));
}

__device__ __forceinline__ uint32_t sptr(const float* p) {
    return (uint32_t)__cvta_generic_to_shared(p);
}

__device__ __forceinline__ void ldsm4(unsigned& r0, unsigned& r1, unsigned& r2, unsigned& r3,
                                      uint32_t a) {
    asm volatile("ldmatrix.sync.aligned.m8n8.x4.shared.b16 {%0,%1,%2,%3}, [%4];\n"
                 : "=r"(r0), "=r"(r1), "=r"(r2), "=r"(r3) : "r"(a));
}

__device__ __forceinline__ void ldsm2(unsigned& r0, unsigned& r1, uint32_t a) {
    asm volatile("ldmatrix.sync.aligned.m8n8.x2.shared.b16 {%0,%1}, [%2];\n"
                 : "=r"(r0), "=r"(r1) : "r"(a));
}

__device__ __forceinline__ void cpa16(uint32_t d, const float* s) {
    asm volatile("cp.async.cg.shared.global [%0], [%1], 16;\n" :: "r"(d), "l"(s));
}
__device__ __forceinline__ void cpa_commit() {
    asm volatile("cp.async.commit_group;\n");
}
template <int N> __device__ __forceinline__ void cpa_wait() {
    asm volatile("cp.async.wait_group %0;\n" :: "n"(N));
}

// ---------------- kernel W: pre-round W1, W2 to tf32 ----------------
__global__ __launch_bounds__(256) void k_prew(const float* __restrict__ W1,
                                              const float* __restrict__ W2) {
    const int i = blockIdx.x * 256 + threadIdx.x;
    const int stride = gridDim.x * 256;
    for (int idx = i; idx < K1 * N1 / 4; idx += stride)
        *(float4*)(g_w1r + (size_t)idx * 4) = tf32r4(*(const float4*)(W1 + (size_t)idx * 4));
    for (int idx = i; idx < CDIM * CDIM / 4; idx += stride)
        *(float4*)(g_w2r + (size_t)idx * 4) = tf32r4(*(const float4*)(W2 + (size_t)idx * 4));
}

// ---------------- kernel B: bias table -> quad-fragment layout ----------------
__global__ __launch_bounds__(256) void k_biasq(const float* __restrict__ table,
                                               const int* __restrict__ pidx) {
    int gi = blockIdx.x * 256 + threadIdx.x;
    if (gi >= NW * HEADS * 9 * 2 * 9 * 32) return;
    int lane = gi & 31;
    int nt   = (gi >> 5) % 9;
    int rest = gi / 288;
    int cb   = rest & 1;  rest >>= 1;
    int mt   = rest % 9;  rest /= 9;
    int h    = rest % 6;
    int nw   = rest / 6;
    int r0 = mt * 16 + (lane >> 2);
    int r1 = r0 + 8;
    int c  = cb * 72 + nt * 8 + (lane & 3) * 2;
    int hh = nw * HEADS + h;
    float4 o;
    o.x = table[(size_t)pidx[r0 * LW + c]     * TABNH + hh];
    o.y = table[(size_t)pidx[r0 * LW + c + 1] * TABNH + hh];
    o.z = table[(size_t)pidx[r1 * LW + c]     * TABNH + hh];
    o.w = table[(size_t)pidx[r1 * LW + c + 1] * TABNH + hh];
    *(float4*)(g_biasQ + (size_t)gi * 4) = o;
}

// ---------------- kernel M: mask -> quad-fragment layout ----------------
__global__ __launch_bounds__(256) void k_maskq(const float* __restrict__ mask) {
    int gi = blockIdx.x * 256 + threadIdx.x;
    if (gi >= BTOT * 9 * 2 * 9 * 32) return;
    int lane = gi & 31;
    int nt   = (gi >> 5) % 9;
    int rest = gi / 288;
    int cb   = rest & 1;  rest >>= 1;
    int mt   = rest % 9;
    int w    = rest / 9;
    int r0 = mt * 16 + (lane >> 2);
    int r1 = r0 + 8;
    int c  = cb * 72 + nt * 8 + (lane & 3) * 2;
    const float* mp = mask + (size_t)w * LW * LW;
    float4 o;
    o.x = mp[r0 * LW + c];
    o.y = mp[r0 * LW + c + 1];
    o.z = mp[r1 * LW + c];
    o.w = mp[r1 * LW + c + 1];
    *(float4*)(g_maskQ + (size_t)gi * 4) = o;
}

// ====== GEMM: block 128x96, 256 thr (8 warps, 4m x 2n), warp m32 x n48 ======
// 2-stage cp.async, 1 barrier per k-tile, forced 3 CTAs/SM.
#define STG 2
#define A_ST (128 * 36)
#define B_ST (32 * 104)
#define GEMM_SMEM (STG * (A_ST + B_ST) * 4)     // 63,488 bytes -> 3 CTAs/SM

// ---------------- kernel 1: QKV = x @ W1r + b1 (A rounded in-register) ----------------
__global__ __launch_bounds__(256, 3) void k_qkv(const float* __restrict__ x,
                                                const float* __restrict__ b1) {
    extern __shared__ __align__(16) float smg[];
    float* As = smg;
    float* Bs = smg + STG * A_ST;

    const int tid  = threadIdx.x;
    const int lane = tid & 31, wid = tid >> 5;
    const int g = lane >> 2, tg = lane & 3;
    const int wm = wid & 3, wn = wid >> 2;
    const int mblk = blockIdx.y * 128;
    const int nblk = blockIdx.x * 96;

    auto load_stage = [&](int s, int kt) {
        const int k0 = kt * 32;
        float* Ad = As + s * A_ST;
        float* Bd = Bs + s * B_ST;
#pragma unroll
        for (int i = 0; i < 4; i++) {               // A: 1024 float4 (128 x 32)
            int idx = tid + 256 * i;
            int r = idx >> 3, kc = (idx & 7) << 2;
            cpa16(sptr(Ad + r * 36 + kc), x + (size_t)(mblk + r) * K1 + k0 + kc);
        }
#pragma unroll
        for (int i = 0; i < 3; i++) {               // B: 768 float4 (32 x 96, k-major)
            int idx = tid + 256 * i;
            int kr = idx / 24, nc = (idx % 24) << 2;
            cpa16(sptr(Bd + kr * 104 + nc), g_w1r + (size_t)(k0 + kr) * N1 + nblk + nc);
        }
        cpa_commit();
    };

    load_stage(0, 0);

    float acc[2][6][4];
#pragma unroll
    for (int i = 0; i < 2; i++)
#pragma unroll
        for (int j = 0; j < 6; j++)
#pragma unroll
            for (int r = 0; r < 4; r++) acc[i][j][r] = 0.f;

#pragma unroll 1
    for (int kt = 0; kt < 6; kt++) {
        __syncthreads();                            // releases buf[(kt+1)%2] for writing
        if (kt < 5) {
            load_stage((kt + 1) & 1, kt + 1);
            cpa_wait<1>();                          // stage kt complete; kt+1 in flight
        } else {
            cpa_wait<0>();
        }
        __syncthreads();                            // all see stage kt complete

        float* Ac = As + (kt & 1) * A_ST;
        float* Bc = Bs + (kt & 1) * B_ST;
#pragma unroll
        for (int kk = 0; kk < 4; kk++) {
            const int kb = kk * 8;
            unsigned a[2][4];
#pragma unroll
            for (int mi = 0; mi < 2; mi++) {
                int arow = wm * 32 + mi * 16 + (lane & 15);
                int acol = kb + ((lane & 16) ? 4 : 0);
                ldsm4(a[mi][0], a[mi][1], a[mi][2], a[mi][3], sptr(Ac + arow * 36 + acol));
#pragma unroll
                for (int j = 0; j < 4; j++) a[mi][j] = tf32u(a[mi][j]);   // round x frags
            }
#pragma unroll
            for (int ni = 0; ni < 6; ni++) {
                int c0 = wn * 48 + ni * 8;
                unsigned b0 = __float_as_uint(Bc[(kb + tg) * 104 + c0 + g]);
                unsigned b1v = __float_as_uint(Bc[(kb + tg + 4) * 104 + c0 + g]);
#pragma unroll
                for (int mi = 0; mi < 2; mi++)
                    mma8(acc[mi][ni], a[mi][0], a[mi][1], a[mi][2], a[mi][3], b0, b1v);
            }
        }
    }

    const float SCALE = 0.17677669529663687f;
#pragma unroll
    for (int mi = 0; mi < 2; mi++)
#pragma unroll
        for (int ni = 0; ni < 6; ni++)
#pragma unroll
            for (int r2 = 0; r2 < 2; r2++) {
                int mrow = mblk + wm * 32 + mi * 16 + g + r2 * 8;
                int n    = nblk + wn * 48 + ni * 8 + tg * 2;
                float v0 = acc[mi][ni][r2 * 2 + 0] + b1[n];
                float v1 = acc[mi][ni][r2 * 2 + 1] + b1[n + 1];
                int which = n / 192;
                int nm    = n % 192;
                int head  = nm / 32;
                int d     = nm & 31;
                int win   = mrow / LW;
                int l     = mrow - win * LW;
                if (which == 0) {
                    size_t dst = (((size_t)win * HEADS + head) * LW + l) * HD + d;
                    *(float2*)(g_q + dst) = make_float2(tf32r(v0 * SCALE), tf32r(v1 * SCALE));
                } else if (which == 1) {
                    size_t dst = (((size_t)win * HEADS + head) * LW + l) * HD + d;
                    *(float2*)(g_k + dst) = make_float2(tf32r(v0), tf32r(v1));
                } else {
                    size_t baset = ((size_t)win * HEADS + head) * (size_t)(HD * LW);
                    g_v[baset + (size_t)d * LW + l]       = tf32r(v0);
                    g_v[baset + (size_t)(d + 1) * LW + l] = tf32r(v1);
                }
            }
}

// ---------------- kernel 2: FA2-style fused attention (quad-layout bias/mask) ----------------
#define SMEM_ATT ((LW*36 + LW*36 + HD*148) * 4)

__global__ __launch_bounds__(288, 2) void k_attn() {
    extern __shared__ __align__(16) float sm[];
    float* Qs = sm;                  // [144][36]
    float* Ks = Qs + LW * 36;        // [144][36]
    float* Vt = Ks + LW * 36;        // [32][148]

    const int h = blockIdx.x;
    const int w = blockIdx.y;
    const int nwi = w / WWINS;
    const int tid = threadIdx.x, lane = tid & 31, wid = tid >> 5;   // wid 0..8 (== mt)
    const int g = lane >> 2, tg = lane & 3;

    const size_t base = ((size_t)w * HEADS + h) * LW * HD;
    float* outp = g_att + (size_t)w * LW * CDIM + h * HD;

    for (int idx = tid; idx < LW * HD / 4; idx += 288) {
        int l = idx >> 3, dc = (idx & 7) << 2;
        *(float4*)&Qs[l * 36 + dc] = *(const float4*)(g_q + base + (size_t)idx * 4);
        *(float4*)&Ks[l * 36 + dc] = *(const float4*)(g_k + base + (size_t)idx * 4);
        int d = idx / 36, lc = (idx % 36) * 4;
        *(float4*)&Vt[d * 148 + lc] = *(const float4*)(g_v + base + (size_t)idx * 4);
    }
    __syncthreads();

    const int m0 = wid * 16;
    unsigned aq[4][4];
    {
        int arow = m0 + (lane & 15);
#pragma unroll
        for (int kk = 0; kk < 4; kk++) {
            int acol = kk * 8 + ((lane & 16) ? 4 : 0);
            ldsm4(aq[kk][0], aq[kk][1], aq[kk][2], aq[kk][3], sptr(Qs + arow * 36 + acol));
        }
    }

    const int r0 = m0 + g, r1 = r0 + 8;
    float mr0 = -1e30f, mr1 = -1e30f;
    float lr0 = 0.f,    lr1 = 0.f;
    float oacc[4][4];
#pragma unroll
    for (int ni = 0; ni < 4; ni++)
#pragma unroll
        for (int r = 0; r < 4; r++) oacc[ni][r] = 0.f;

    const int srcA = (lane & ~3) | (tg >> 1);
    const int srcB = srcA + 2;

#pragma unroll
    for (int cb = 0; cb < 2; cb++) {
        const int c0 = cb * 72;
        const float4* bqc = (const float4*)g_biasQ
            + ((((size_t)(nwi * HEADS + h) * 9 + wid) * 2 + cb) * 288) + lane;
        const float4* mqc = (const float4*)g_maskQ
            + ((((size_t)w * 9 + wid) * 2 + cb) * 288) + lane;

        float sacc[9][4];
#pragma unroll
        for (int nt = 0; nt < 9; nt++)
#pragma unroll
            for (int r = 0; r < 4; r++) sacc[nt][r] = 0.f;

        // --- QK: 4 x n16 via ldsm4 + 1 leftover n8 via ldsm2 ---
#pragma unroll
        for (int ntp = 0; ntp < 4; ntp++) {
            const int brow = c0 + ntp * 16 + (lane & 7) + ((lane & 16) ? 8 : 0);
#pragma unroll
            for (int kk = 0; kk < 4; kk++) {
                const int bcol = kk * 8 + ((lane & 8) ? 4 : 0);
                unsigned b0, b1, b2, b3;
                ldsm4(b0, b1, b2, b3, sptr(Ks + brow * 36 + bcol));
                mma8(sacc[ntp * 2],     aq[kk][0], aq[kk][1], aq[kk][2], aq[kk][3], b0, b1);
                mma8(sacc[ntp * 2 + 1], aq[kk][0], aq[kk][1], aq[kk][2], aq[kk][3], b2, b3);
            }
        }
        {
            const int nrow = c0 + 64 + (lane & 7);
#pragma unroll
            for (int kk = 0; kk < 4; kk++) {
                unsigned b0, b1;
                ldsm2(b0, b1, sptr(Ks + nrow * 36 + kk * 8 + ((lane & 8) ? 4 : 0)));
                mma8(sacc[8], aq[kk][0], aq[kk][1], aq[kk][2], aq[kk][3], b0, b1);
            }
        }

#pragma unroll
        for (int nt = 0; nt < 9; nt++) {
            float4 bv = bqc[nt * 32];
            float4 mv = mqc[nt * 32];
            sacc[nt][0] += bv.x + mv.x;
            sacc[nt][1] += bv.y + mv.y;
            sacc[nt][2] += bv.z + mv.z;
            sacc[nt][3] += bv.w + mv.w;
        }

        float mx0 = -1e30f, mx1 = -1e30f;
#pragma unroll
        for (int nt = 0; nt < 9; nt++) {
            mx0 = fmaxf(mx0, fmaxf(sacc[nt][0], sacc[nt][1]));
            mx1 = fmaxf(mx1, fmaxf(sacc[nt][2], sacc[nt][3]));
        }
        mx0 = fmaxf(mx0, __shfl_xor_sync(0xffffffffu, mx0, 1));
        mx0 = fmaxf(mx0, __shfl_xor_sync(0xffffffffu, mx0, 2));
        mx1 = fmaxf(mx1, __shfl_xor_sync(0xffffffffu, mx1, 1));
        mx1 = fmaxf(mx1, __shfl_xor_sync(0xffffffffu, mx1, 2));
        const float mn0 = fmaxf(mr0, mx0);
        const float mn1 = fmaxf(mr1, mx1);
        const float sc0 = __expf(mr0 - mn0);
        const float sc1 = __expf(mr1 - mn1);
        mr0 = mn0; mr1 = mn1;

        float sum0 = 0.f, sum1 = 0.f;
#pragma unroll
        for (int nt = 0; nt < 9; nt++) {
            sacc[nt][0] = __expf(sacc[nt][0] - mn0);
            sacc[nt][1] = __expf(sacc[nt][1] - mn0);
            sacc[nt][2] = __expf(sacc[nt][2] - mn1);
            sacc[nt][3] = __expf(sacc[nt][3] - mn1);
            sum0 += sacc[nt][0] + sacc[nt][1];
            sum1 += sacc[nt][2] + sacc[nt][3];
        }
        sum0 += __shfl_xor_sync(0xffffffffu, sum0, 1);
        sum0 += __shfl_xor_sync(0xffffffffu, sum0, 2);
        sum1 += __shfl_xor_sync(0xffffffffu, sum1, 1);
        sum1 += __shfl_xor_sync(0xffffffffu, sum1, 2);
        lr0 = lr0 * sc0 + sum0;
        lr1 = lr1 * sc1 + sum1;

#pragma unroll
        for (int ni = 0; ni < 4; ni++) {
            oacc[ni][0] *= sc0; oacc[ni][1] *= sc0;
            oacc[ni][2] *= sc1; oacc[ni][3] *= sc1;
        }

#pragma unroll
        for (int nt = 0; nt < 9; nt++)
#pragma unroll
            for (int r = 0; r < 4; r++) sacc[nt][r] = tf32r(sacc[nt][r]);

        // --- PV: P from regs via quad shuffles; V frags via 2 ldsm4 per ks ---
#pragma unroll
        for (int ks = 0; ks < 9; ks++) {
            float v00 = __shfl_sync(0xffffffffu, sacc[ks][0], srcA);
            float v01 = __shfl_sync(0xffffffffu, sacc[ks][1], srcA);
            float v10 = __shfl_sync(0xffffffffu, sacc[ks][2], srcA);
            float v11 = __shfl_sync(0xffffffffu, sacc[ks][3], srcA);
            float v20 = __shfl_sync(0xffffffffu, sacc[ks][0], srcB);
            float v21 = __shfl_sync(0xffffffffu, sacc[ks][1], srcB);
            float v30 = __shfl_sync(0xffffffffu, sacc[ks][2], srcB);
            float v31 = __shfl_sync(0xffffffffu, sacc[ks][3], srcB);
            unsigned a0 = __float_as_uint((tg & 1) ? v01 : v00);
            unsigned a1 = __float_as_uint((tg & 1) ? v11 : v10);
            unsigned a2 = __float_as_uint((tg & 1) ? v21 : v20);
            unsigned a3 = __float_as_uint((tg & 1) ? v31 : v30);
            const int kcol = c0 + ks * 8 + ((lane & 8) ? 4 : 0);
#pragma unroll
            for (int nip = 0; nip < 2; nip++) {
                const int vrow = nip * 16 + (lane & 7) + ((lane & 16) ? 8 : 0);
                unsigned b0, b1, b2, b3;
                ldsm4(b0, b1, b2, b3, sptr(Vt + vrow * 148 + kcol));
                mma8(oacc[nip * 2],     a0, a1, a2, a3, b0, b1);
                mma8(oacc[nip * 2 + 1], a0, a1, a2, a3, b2, b3);
            }
        }
    }

    const float inv0 = 1.f / lr0;
    const float inv1 = 1.f / lr1;
#pragma unroll
    for (int ni = 0; ni < 4; ni++) {
        int d = ni * 8 + tg * 2;
        *(float2*)(outp + (size_t)r0 * CDIM + d) =
            make_float2(tf32r(oacc[ni][0] * inv0), tf32r(oacc[ni][1] * inv0));
        *(float2*)(outp + (size_t)r1 * CDIM + d) =
            make_float2(tf32r(oacc[ni][2] * inv1), tf32r(oacc[ni][3] * inv1));
    }
}

// ---------------- kernel 3: out = g_att @ W2r + b2 ----------------
__global__ __launch_bounds__(256, 3) void k_proj(const float* __restrict__ b2,
                                                 float* __restrict__ out) {
    extern __shared__ __align__(16) float smg[];
    float* As = smg;
    float* Bs = smg + STG * A_ST;

    const int tid  = threadIdx.x;
    const int lane = tid & 31, wid = tid >> 5;
    const int g = lane >> 2, tg = lane & 3;
    const int wm = wid & 3, wn = wid >> 2;
    const int mblk = blockIdx.y * 128;
    const int nblk = blockIdx.x * 96;

    auto load_stage = [&](int s, int kt) {
        const int k0 = kt * 32;
        float* Ad = As + s * A_ST;
        float* Bd = Bs + s * B_ST;
#pragma unroll
        for (int i = 0; i < 4; i++) {
            int idx = tid + 256 * i;
            int r = idx >> 3, kc = (idx & 7) << 2;
            cpa16(sptr(Ad + r * 36 + kc), g_att + (size_t)(mblk + r) * CDIM + k0 + kc);
        }
#pragma unroll
        for (int i = 0; i < 3; i++) {
            int idx = tid + 256 * i;
            int kr = idx / 24, nc = (idx % 24) << 2;
            cpa16(sptr(Bd + kr * 104 + nc), g_w2r + (size_t)(k0 + kr) * CDIM + nblk + nc);
        }
        cpa_commit();
    };

    load_stage(0, 0);

    float acc[2][6][4];
#pragma unroll
    for (int i = 0; i < 2; i++)
#pragma unroll
        for (int j = 0; j < 6; j++)
#pragma unroll
            for (int r = 0; r < 4; r++) acc[i][j][r] = 0.f;

#pragma unroll 1
    for (int kt = 0; kt < 6; kt++) {
        __syncthreads();
        if (kt < 5) {
            load_stage((kt + 1) & 1, kt + 1);
            cpa_wait<1>();
        } else {
            cpa_wait<0>();
        }
        __syncthreads();

        float* Ac = As + (kt & 1) * A_ST;
        float* Bc = Bs + (kt & 1) * B_ST;
#pragma unroll
        for (int kk = 0; kk < 4; kk++) {
            const int kb = kk * 8;
            unsigned a[2][4];
#pragma unroll
            for (int mi = 0; mi < 2; mi++) {
                int arow = wm * 32 + mi * 16 + (lane & 15);
                int acol = kb + ((lane & 16) ? 4 : 0);
                ldsm4(a[mi][0], a[mi][1], a[mi][2], a[mi][3], sptr(Ac + arow * 36 + acol));
            }
#pragma unroll
            for (int ni = 0; ni < 6; ni++) {
                int c0 = wn * 48 + ni * 8;
                unsigned b0 = __float_as_uint(Bc[(kb + tg) * 104 + c0 + g]);
                unsigned b1v = __float_as_uint(Bc[(kb + tg + 4) * 104 + c0 + g]);
#pragma unroll
                for (int mi = 0; mi < 2; mi++)
                    mma8(acc[mi][ni], a[mi][0], a[mi][1], a[mi][2], a[mi][3], b0, b1v);
            }
        }
    }

#pragma unroll
    for (int mi = 0; mi < 2; mi++)
#pragma unroll
        for (int ni = 0; ni < 6; ni++)
#pragma unroll
            for (int r2 = 0; r2 < 2; r2++) {
                int mrow = mblk + wm * 32 + mi * 16 + g + r2 * 8;
                int n    = nblk + wn * 48 + ni * 8 + tg * 2;
                float v0 = acc[mi][ni][r2 * 2 + 0] + b2[n];
                float v1 = acc[mi][ni][r2 * 2 + 1] + b2[n + 1];
                *(float2*)(out + (size_t)mrow * CDIM + n) = make_float2(v0, v1);
            }
}

// ---------------- launch ----------------
extern "C" void kernel_launch(void* const* d_in, const int* in_sizes, int n_in,
                              void* d_out, int out_size) {
    const float* x     = (const float*)d_in[0];
    const float* mask  = (const float*)d_in[1];
    const float* W1    = (const float*)d_in[2];
    const float* b1    = (const float*)d_in[3];
    const float* W2    = (const float*)d_in[4];
    const float* b2    = (const float*)d_in[5];
    const float* table = (const float*)d_in[6];
    const int*   pidx  = (const int*)d_in[7];

    cudaFuncSetAttribute(k_attn, cudaFuncAttributeMaxDynamicSharedMemorySize, SMEM_ATT);
    cudaFuncSetAttribute(k_qkv,  cudaFuncAttributeMaxDynamicSharedMemorySize, GEMM_SMEM);
    cudaFuncSetAttribute(k_proj, cudaFuncAttributeMaxDynamicSharedMemorySize, GEMM_SMEM);

    k_prew<<<108, 256>>>(W1, W2);
    k_biasq<<<(NW * HEADS * 9 * 2 * 9 * 32 + 255) / 256, 256>>>(table, pidx);
    k_maskq<<<(BTOT * 9 * 2 * 9 * 32 + 255) / 256, 256>>>(mask);
    k_qkv<<<dim3(N1 / 96, M1 / 128), 256, GEMM_SMEM>>>(x, b1);
    k_attn<<<dim3(HEADS, BTOT), 288, SMEM_ATT>>>();
    k_proj<<<dim3(CDIM / 96, M1 / 128), 256, GEMM_SMEM>>>(b2, (float*)d_out);
}

// round 15
// speedup vs baseline: 1.3991x; 1.3991x over previous
#include <cuda_runtime.h>
#include <cuda_fp16.h>
#include <cstdint>

// ---------------- problem constants (static shapes) ----------------
#define HEADS 6
#define LW    144
#define HD    32
#define CDIM  192
#define NW    64
#define WWINS 15
#define BTOT  960
#define M1    (BTOT*LW)      // 138240
#define N1    576
#define K1    192
#define TABNH (NW*HEADS)

// ---------------- scratch (device globals; no allocations) ----------------
__device__ __half g_xh[(size_t)M1*K1];            // x converted to fp16
__device__ __half g_q[(size_t)BTOT*HEADS*LW*HD];
__device__ __half g_k[(size_t)BTOT*HEADS*LW*HD];
__device__ __half g_v[(size_t)BTOT*HEADS*LW*HD];  // TRANSPOSED: [w][h][d][l]
__device__ __half g_att[(size_t)M1*CDIM];         // fp16 att output
__device__ __half g_w1t[(size_t)N1*K1];           // W1 transposed [n][k] fp16
__device__ __half g_w2t[(size_t)CDIM*CDIM];       // W2 transposed [n][k] fp16
// quad-fragment-ordered bias/mask (fp32): [grp][mt(9)][cb(2)][nt(9)][lane(32)][4]
__device__ float g_biasQ[(size_t)NW*HEADS*9*2*9*32*4];
__device__ float g_maskQ[(size_t)BTOT*9*2*9*32*4];

// ---------------- helpers ----------------
__device__ __forceinline__ unsigned pack2h(float lo, float hi) {
    __half2 h = __floats2half2_rn(lo, hi);
    return *reinterpret_cast<unsigned*>(&h);
}

__device__ __forceinline__ void mma16(float c[4],
                                      unsigned a0, unsigned a1, unsigned a2, unsigned a3,
                                      unsigned b0, unsigned b1) {
    asm volatile(
        "mma.sync.aligned.m16n8k16.row.col.f32.f16.f16.f32 "
        "{%0,%1,%2,%3}, {%4,%5,%6,%7}, {%8,%9}, {%0,%1,%2,%3};\n"
        : "+f"(c[0]), "+f"(c[1]), "+f"(c[2]), "+f"(c[3])
        : "r"(a0), "r"(a1), "r"(a2), "r"(a3), "r"(b0), "r"(b1));
}

__device__ __forceinline__ void mma8h(float c[4],
                                      unsigned a0, unsigned a1, unsigned b0) {
    asm volatile(
        "mma.sync.aligned.m16n8k8.row.col.f32.f16.f16.f32 "
        "{%0,%1,%2,%3}, {%4,%5}, {%6}, {%0,%1,%2,%3};\n"
        : "+f"(c[0]), "+f"(c[1]), "+f"(c[2]), "+f"(c[3])
        : "r"(a0), "r"(a1), "r"(b0));
}

__device__ __forceinline__ uint32_t sptr(const void* p) {
    return (uint32_t)__cvta_generic_to_shared(p);
}

__device__ __forceinline__ void ldsm4(unsigned& r0, unsigned& r1, unsigned& r2, unsigned& r3,
                                      uint32_t a) {
    asm volatile("ldmatrix.sync.aligned.m8n8.x4.shared.b16 {%0,%1,%2,%3}, [%4];\n"
                 : "=r"(r0), "=r"(r1), "=r"(r2), "=r"(r3) : "r"(a));
}

__device__ __forceinline__ void ldsm2(unsigned& r0, unsigned& r1, uint32_t a) {
    asm volatile("ldmatrix.sync.aligned.m8n8.x2.shared.b16 {%0,%1}, [%2];\n"
                 : "=r"(r0), "=r"(r1) : "r"(a));
}

__device__ __forceinline__ void cpa16(uint32_t d, const void* s) {
    asm volatile("cp.async.cg.shared.global [%0], [%1], 16;\n" :: "r"(d), "l"(s));
}
__device__ __forceinline__ void cpa_commit() {
    asm volatile("cp.async.commit_group;\n");
}
template <int N> __device__ __forceinline__ void cpa_wait() {
    asm volatile("cp.async.wait_group %0;\n" :: "n"(N));
}

// ---------------- kernel P: convert x to fp16; transpose+convert W1, W2 ----------------
__global__ __launch_bounds__(256) void k_preh(const float* __restrict__ x,
                                              const float* __restrict__ W1,
                                              const float* __restrict__ W2) {
    const size_t i = (size_t)blockIdx.x * 256 + threadIdx.x;
    const size_t stride = (size_t)gridDim.x * 256;
    for (size_t idx = i; idx < (size_t)M1 * K1 / 4; idx += stride) {
        float4 v = *(const float4*)(x + idx * 4);
        unsigned u0 = pack2h(v.x, v.y), u1 = pack2h(v.z, v.w);
        *(uint2*)(g_xh + idx * 4) = make_uint2(u0, u1);
    }
    for (size_t gi = i; gi < (size_t)N1 * K1; gi += stride) {
        int n = (int)(gi / K1), k = (int)(gi % K1);
        g_w1t[gi] = __float2half_rn(W1[(size_t)k * N1 + n]);
    }
    for (size_t gi = i; gi < (size_t)CDIM * CDIM; gi += stride) {
        int n = (int)(gi / CDIM), k = (int)(gi % CDIM);
        g_w2t[gi] = __float2half_rn(W2[(size_t)k * CDIM + n]);
    }
}

// ---------------- kernel B: bias table -> quad-fragment layout ----------------
__global__ __launch_bounds__(256) void k_biasq(const float* __restrict__ table,
                                               const int* __restrict__ pidx) {
    int gi = blockIdx.x * 256 + threadIdx.x;
    if (gi >= NW * HEADS * 9 * 2 * 9 * 32) return;
    int lane = gi & 31;
    int nt   = (gi >> 5) % 9;
    int rest = gi / 288;
    int cb   = rest & 1;  rest >>= 1;
    int mt   = rest % 9;  rest /= 9;
    int h    = rest % 6;
    int nw   = rest / 6;
    int r0 = mt * 16 + (lane >> 2);
    int r1 = r0 + 8;
    int c  = cb * 72 + nt * 8 + (lane & 3) * 2;
    int hh = nw * HEADS + h;
    float4 o;
    o.x = table[(size_t)pidx[r0 * LW + c]     * TABNH + hh];
    o.y = table[(size_t)pidx[r0 * LW + c + 1] * TABNH + hh];
    o.z = table[(size_t)pidx[r1 * LW + c]     * TABNH + hh];
    o.w = table[(size_t)pidx[r1 * LW + c + 1] * TABNH + hh];
    *(float4*)(g_biasQ + (size_t)gi * 4) = o;
}

// ---------------- kernel M: mask -> quad-fragment layout ----------------
__global__ __launch_bounds__(256) void k_maskq(const float* __restrict__ mask) {
    int gi = blockIdx.x * 256 + threadIdx.x;
    if (gi >= BTOT * 9 * 2 * 9 * 32) return;
    int lane = gi & 31;
    int nt   = (gi >> 5) % 9;
    int rest = gi / 288;
    int cb   = rest & 1;  rest >>= 1;
    int mt   = rest % 9;
    int w    = rest / 9;
    int r0 = mt * 16 + (lane >> 2);
    int r1 = r0 + 8;
    int c  = cb * 72 + nt * 8 + (lane & 3) * 2;
    const float* mp = mask + (size_t)w * LW * LW;
    float4 o;
    o.x = mp[r0 * LW + c];
    o.y = mp[r0 * LW + c + 1];
    o.z = mp[r1 * LW + c];
    o.w = mp[r1 * LW + c + 1];
    *(float4*)(g_maskQ + (size_t)gi * 4) = o;
}

// ====== fp16 GEMM: block 128x96, 256 thr (8 warps, 4m x 2n), warp m32 x n48 ======
// 2-stage cp.async, 3 CTAs/SM. A [m][k] stride 40h, B [n][k] stride 40h.
#define STG 2
#define A_ST (128 * 40)                          // halves
#define B_ST (96 * 40)
#define GEMM_SMEM (STG * (A_ST + B_ST) * 2)      // 35,840 bytes

// ---------------- kernel 1: QKV = xh @ W1 + b1 (scatter epilogue) ----------------
__global__ __launch_bounds__(256, 3) void k_qkv(const float* __restrict__ b1) {
    extern __shared__ __align__(16) __half smh[];
    __half* As = smh;
    __half* Bs = smh + STG * A_ST;

    const int tid  = threadIdx.x;
    const int lane = tid & 31, wid = tid >> 5;
    const int g = lane >> 2, tg = lane & 3;
    const int wm = wid & 3, wn = wid >> 2;
    const int mblk = blockIdx.y * 128;
    const int nblk = blockIdx.x * 96;

    auto load_stage = [&](int s, int kt) {
        const int k0 = kt * 32;
        __half* Ad = As + s * A_ST;
        __half* Bd = Bs + s * B_ST;
#pragma unroll
        for (int i = 0; i < 2; i++) {               // A: 512 cp16 (128 x 32h)
            int idx = tid + 256 * i;
            int r = idx >> 2, kc = (idx & 3) << 3;
            cpa16(sptr(Ad + r * 40 + kc), g_xh + (size_t)(mblk + r) * K1 + k0 + kc);
        }
#pragma unroll
        for (int i = 0; i < 2; i++) {               // B: 384 cp16 (96 x 32h, n-major)
            int idx = tid + 256 * i;
            if (idx < 384) {
                int n = idx >> 2, kc = (idx & 3) << 3;
                cpa16(sptr(Bd + n * 40 + kc), g_w1t + (size_t)(nblk + n) * K1 + k0 + kc);
            }
        }
        cpa_commit();
    };

    load_stage(0, 0);

    float acc[2][6][4];
#pragma unroll
    for (int i = 0; i < 2; i++)
#pragma unroll
        for (int j = 0; j < 6; j++)
#pragma unroll
            for (int r = 0; r < 4; r++) acc[i][j][r] = 0.f;

#pragma unroll 1
    for (int kt = 0; kt < 6; kt++) {
        __syncthreads();
        if (kt < 5) {
            load_stage((kt + 1) & 1, kt + 1);
            cpa_wait<1>();
        } else {
            cpa_wait<0>();
        }
        __syncthreads();

        __half* Ac = As + (kt & 1) * A_ST;
        __half* Bc = Bs + (kt & 1) * B_ST;
#pragma unroll
        for (int kk = 0; kk < 2; kk++) {            // two k16 steps
            unsigned a[2][4];
#pragma unroll
            for (int mi = 0; mi < 2; mi++) {
                int arow = wm * 32 + mi * 16 + (lane & 7) + ((lane & 8) ? 8 : 0);
                int acol = kk * 16 + ((lane & 16) ? 8 : 0);
                ldsm4(a[mi][0], a[mi][1], a[mi][2], a[mi][3], sptr(Ac + arow * 40 + acol));
            }
#pragma unroll
            for (int nj = 0; nj < 3; nj++) {        // three n16 tiles
                int brow = wn * 48 + nj * 16 + (lane & 7) + ((lane & 16) ? 8 : 0);
                int bcol = kk * 16 + ((lane & 8) ? 8 : 0);
                unsigned b0, b1, b2, b3;
                ldsm4(b0, b1, b2, b3, sptr(Bc + brow * 40 + bcol));
#pragma unroll
                for (int mi = 0; mi < 2; mi++) {
                    mma16(acc[mi][nj * 2],     a[mi][0], a[mi][1], a[mi][2], a[mi][3], b0, b1);
                    mma16(acc[mi][nj * 2 + 1], a[mi][0], a[mi][1], a[mi][2], a[mi][3], b2, b3);
                }
            }
        }
    }

    const float SCALE = 0.17677669529663687f;
#pragma unroll
    for (int mi = 0; mi < 2; mi++)
#pragma unroll
        for (int ni = 0; ni < 6; ni++)
#pragma unroll
            for (int r2 = 0; r2 < 2; r2++) {
                int mrow = mblk + wm * 32 + mi * 16 + g + r2 * 8;
                int n    = nblk + wn * 48 + ni * 8 + tg * 2;
                float v0 = acc[mi][ni][r2 * 2 + 0] + b1[n];
                float v1 = acc[mi][ni][r2 * 2 + 1] + b1[n + 1];
                int which = n / 192;
                int nm    = n % 192;
                int head  = nm / 32;
                int d     = nm & 31;
                int win   = mrow / LW;
                int l     = mrow - win * LW;
                if (which == 0) {
                    size_t dst = (((size_t)win * HEADS + head) * LW + l) * HD + d;
                    *reinterpret_cast<__half2*>(g_q + dst) =
                        __floats2half2_rn(v0 * SCALE, v1 * SCALE);
                } else if (which == 1) {
                    size_t dst = (((size_t)win * HEADS + head) * LW + l) * HD + d;
                    *reinterpret_cast<__half2*>(g_k + dst) = __floats2half2_rn(v0, v1);
                } else {
                    size_t baset = ((size_t)win * HEADS + head) * (size_t)(HD * LW);
                    g_v[baset + (size_t)d * LW + l]       = __float2half_rn(v0);
                    g_v[baset + (size_t)(d + 1) * LW + l] = __float2half_rn(v1);
                }
            }
}

// ---------------- kernel 2: FA2 fused attention, fp16 operands ----------------
// smem (halves): Qs[144][40] + Ks[144][40] + Vt[32][152]  = 32,768 bytes
#define SMEM_ATT ((LW*40 + LW*40 + HD*152) * 2)

__global__ __launch_bounds__(288, 2) void k_attn() {
    extern __shared__ __align__(16) __half smh[];
    __half* Qs = smh;                 // [144][40]
    __half* Ks = Qs + LW * 40;        // [144][40]
    __half* Vt = Ks + LW * 40;        // [32][152]

    const int h = blockIdx.x;
    const int w = blockIdx.y;
    const int nwi = w / WWINS;
    const int tid = threadIdx.x, lane = tid & 31, wid = tid >> 5;   // wid 0..8 (== mt)
    const int g = lane >> 2, tg = lane & 3;

    const size_t base = ((size_t)w * HEADS + h) * LW * HD;
    __half* outp = g_att + (size_t)w * LW * CDIM + h * HD;

    // ---- fill Q/K [l][d] and Vt [d][l] (uint4 = 8 halves) ----
    for (int idx = tid; idx < 576; idx += 288) {
        int l = idx >> 2, dc = (idx & 3) << 3;
        *(uint4*)&Qs[l * 40 + dc] = *(const uint4*)(g_q + base + (size_t)idx * 8);
        *(uint4*)&Ks[l * 40 + dc] = *(const uint4*)(g_k + base + (size_t)idx * 8);
        int d = idx / 18, lc = (idx % 18) << 3;
        *(uint4*)&Vt[d * 152 + lc] = *(const uint4*)(g_v + base + (size_t)idx * 8);
    }
    __syncthreads();

    // ---- pin this warp's Q rows (m16 x k32) as A-fragments ----
    const int m0 = wid * 16;
    unsigned aq[2][4];
    {
        int arow = m0 + (lane & 7) + ((lane & 8) ? 8 : 0);
#pragma unroll
        for (int kk = 0; kk < 2; kk++) {
            int acol = kk * 16 + ((lane & 16) ? 8 : 0);
            ldsm4(aq[kk][0], aq[kk][1], aq[kk][2], aq[kk][3], sptr(Qs + arow * 40 + acol));
        }
    }

    const int r0 = m0 + g, r1 = r0 + 8;
    float mr0 = -1e30f, mr1 = -1e30f;
    float lr0 = 0.f,    lr1 = 0.f;
    float oacc[4][4];
#pragma unroll
    for (int ni = 0; ni < 4; ni++)
#pragma unroll
        for (int r = 0; r < 4; r++) oacc[ni][r] = 0.f;

#pragma unroll
    for (int cb = 0; cb < 2; cb++) {
        const int c0 = cb * 72;
        const float4* bqc = (const float4*)g_biasQ
            + ((((size_t)(nwi * HEADS + h) * 9 + wid) * 2 + cb) * 288) + lane;
        const float4* mqc = (const float4*)g_maskQ
            + ((((size_t)w * 9 + wid) * 2 + cb) * 288) + lane;

        float sacc[9][4];
#pragma unroll
        for (int nt = 0; nt < 9; nt++)
#pragma unroll
            for (int r = 0; r < 4; r++) sacc[nt][r] = 0.f;

        // --- S = Q K^T (k16 x2 over d=32): 4 n16 ldsm4 + 1 n8 ldsm2 per step ---
#pragma unroll
        for (int kk = 0; kk < 2; kk++) {
#pragma unroll
            for (int ntp = 0; ntp < 4; ntp++) {
                int brow = c0 + ntp * 16 + (lane & 7) + ((lane & 16) ? 8 : 0);
                int bcol = kk * 16 + ((lane & 8) ? 8 : 0);
                unsigned b0, b1, b2, b3;
                ldsm4(b0, b1, b2, b3, sptr(Ks + brow * 40 + bcol));
                mma16(sacc[ntp * 2],     aq[kk][0], aq[kk][1], aq[kk][2], aq[kk][3], b0, b1);
                mma16(sacc[ntp * 2 + 1], aq[kk][0], aq[kk][1], aq[kk][2], aq[kk][3], b2, b3);
            }
            {
                int nrow = c0 + 64 + (lane & 7);
                int ncol = kk * 16 + ((lane & 8) ? 8 : 0);
                unsigned b0, b1;
                ldsm2(b0, b1, sptr(Ks + nrow * 40 + ncol));
                mma16(sacc[8], aq[kk][0], aq[kk][1], aq[kk][2], aq[kk][3], b0, b1);
            }
        }

        // --- + bias + mask (coalesced quad-layout LDG.128) ---
#pragma unroll
        for (int nt = 0; nt < 9; nt++) {
            float4 bv = bqc[nt * 32];
            float4 mv = mqc[nt * 32];
            sacc[nt][0] += bv.x + mv.x;
            sacc[nt][1] += bv.y + mv.y;
            sacc[nt][2] += bv.z + mv.z;
            sacc[nt][3] += bv.w + mv.w;
        }

        // --- online softmax (registers + quad shuffles) ---
        float mx0 = -1e30f, mx1 = -1e30f;
#pragma unroll
        for (int nt = 0; nt < 9; nt++) {
            mx0 = fmaxf(mx0, fmaxf(sacc[nt][0], sacc[nt][1]));
            mx1 = fmaxf(mx1, fmaxf(sacc[nt][2], sacc[nt][3]));
        }
        mx0 = fmaxf(mx0, __shfl_xor_sync(0xffffffffu, mx0, 1));
        mx0 = fmaxf(mx0, __shfl_xor_sync(0xffffffffu, mx0, 2));
        mx1 = fmaxf(mx1, __shfl_xor_sync(0xffffffffu, mx1, 1));
        mx1 = fmaxf(mx1, __shfl_xor_sync(0xffffffffu, mx1, 2));
        const float mn0 = fmaxf(mr0, mx0);
        const float mn1 = fmaxf(mr1, mx1);
        const float sc0 = __expf(mr0 - mn0);
        const float sc1 = __expf(mr1 - mn1);
        mr0 = mn0; mr1 = mn1;

        float sum0 = 0.f, sum1 = 0.f;
#pragma unroll
        for (int nt = 0; nt < 9; nt++) {
            sacc[nt][0] = __expf(sacc[nt][0] - mn0);
            sacc[nt][1] = __expf(sacc[nt][1] - mn0);
            sacc[nt][2] = __expf(sacc[nt][2] - mn1);
            sacc[nt][3] = __expf(sacc[nt][3] - mn1);
            sum0 += sacc[nt][0] + sacc[nt][1];
            sum1 += sacc[nt][2] + sacc[nt][3];
        }
        sum0 += __shfl_xor_sync(0xffffffffu, sum0, 1);
        sum0 += __shfl_xor_sync(0xffffffffu, sum0, 2);
        sum1 += __shfl_xor_sync(0xffffffffu, sum1, 1);
        sum1 += __shfl_xor_sync(0xffffffffu, sum1, 2);
        lr0 = lr0 * sc0 + sum0;
        lr1 = lr1 * sc1 + sum1;

#pragma unroll
        for (int ni = 0; ni < 4; ni++) {
            oacc[ni][0] *= sc0; oacc[ni][1] *= sc0;
            oacc[ni][2] *= sc1; oacc[ni][3] *= sc1;
        }

        // --- O += P V : fp16 C-frag == A-frag layout -> pure register packs ---
#pragma unroll
        for (int ks = 0; ks < 4; ks++) {            // 4 x k16
            unsigned a0 = pack2h(sacc[2*ks][0],     sacc[2*ks][1]);
            unsigned a1 = pack2h(sacc[2*ks][2],     sacc[2*ks][3]);
            unsigned a2 = pack2h(sacc[2*ks + 1][0], sacc[2*ks + 1][1]);
            unsigned a3 = pack2h(sacc[2*ks + 1][2], sacc[2*ks + 1][3]);
            int kcol = c0 + ks * 16 + ((lane & 8) ? 8 : 0);
#pragma unroll
            for (int nip = 0; nip < 2; nip++) {
                int vrow = nip * 16 + (lane & 7) + ((lane & 16) ? 8 : 0);
                unsigned b0, b1, b2, b3;
                ldsm4(b0, b1, b2, b3, sptr(Vt + vrow * 152 + kcol));
                mma16(oacc[nip * 2],     a0, a1, a2, a3, b0, b1);
                mma16(oacc[nip * 2 + 1], a0, a1, a2, a3, b2, b3);
            }
        }
        {                                           // k8 remainder (cols c0+64..71)
            unsigned a0 = pack2h(sacc[8][0], sacc[8][1]);
            unsigned a1 = pack2h(sacc[8][2], sacc[8][3]);
            unsigned b0, b1, b2, b3;
            ldsm4(b0, b1, b2, b3, sptr(Vt + lane * 152 + c0 + 64));
            mma8h(oacc[0], a0, a1, b0);
            mma8h(oacc[1], a0, a1, b1);
            mma8h(oacc[2], a0, a1, b2);
            mma8h(oacc[3], a0, a1, b3);
        }
    }

    // ---- normalize, convert to fp16, store ----
    const float inv0 = 1.f / lr0;
    const float inv1 = 1.f / lr1;
#pragma unroll
    for (int ni = 0; ni < 4; ni++) {
        int d = ni * 8 + tg * 2;
        *reinterpret_cast<__half2*>(outp + (size_t)r0 * CDIM + d) =
            __floats2half2_rn(oacc[ni][0] * inv0, oacc[ni][1] * inv0);
        *reinterpret_cast<__half2*>(outp + (size_t)r1 * CDIM + d) =
            __floats2half2_rn(oacc[ni][2] * inv1, oacc[ni][3] * inv1);
    }
}

// ---------------- kernel 3: out = att(fp16) @ W2 + b2 (fp32 out) ----------------
__global__ __launch_bounds__(256, 3) void k_proj(const float* __restrict__ b2,
                                                 float* __restrict__ out) {
    extern __shared__ __align__(16) __half smh[];
    __half* As = smh;
    __half* Bs = smh + STG * A_ST;

    const int tid  = threadIdx.x;
    const int lane = tid & 31, wid = tid >> 5;
    const int g = lane >> 2, tg = lane & 3;
    const int wm = wid & 3, wn = wid >> 2;
    const int mblk = blockIdx.y * 128;
    const int nblk = blockIdx.x * 96;

    auto load_stage = [&](int s, int kt) {
        const int k0 = kt * 32;
        __half* Ad = As + s * A_ST;
        __half* Bd = Bs + s * B_ST;
#pragma unroll
        for (int i = 0; i < 2; i++) {
            int idx = tid + 256 * i;
            int r = idx >> 2, kc = (idx & 3) << 3;
            cpa16(sptr(Ad + r * 40 + kc), g_att + (size_t)(mblk + r) * CDIM + k0 + kc);
        }
#pragma unroll
        for (int i = 0; i < 2; i++) {
            int idx = tid + 256 * i;
            if (idx < 384) {
                int n = idx >> 2, kc = (idx & 3) << 3;
                cpa16(sptr(Bd + n * 40 + kc), g_w2t + (size_t)(nblk + n) * CDIM + k0 + kc);
            }
        }
        cpa_commit();
    };

    load_stage(0, 0);

    float acc[2][6][4];
#pragma unroll
    for (int i = 0; i < 2; i++)
#pragma unroll
        for (int j = 0; j < 6; j++)
#pragma unroll
            for (int r = 0; r < 4; r++) acc[i][j][r] = 0.f;

#pragma unroll 1
    for (int kt = 0; kt < 6; kt++) {
        __syncthreads();
        if (kt < 5) {
            load_stage((kt + 1) & 1, kt + 1);
            cpa_wait<1>();
        } else {
            cpa_wait<0>();
        }
        __syncthreads();

        __half* Ac = As + (kt & 1) * A_ST;
        __half* Bc = Bs + (kt & 1) * B_ST;
#pragma unroll
        for (int kk = 0; kk < 2; kk++) {
            unsigned a[2][4];
#pragma unroll
            for (int mi = 0; mi < 2; mi++) {
                int arow = wm * 32 + mi * 16 + (lane & 7) + ((lane & 8) ? 8 : 0);
                int acol = kk * 16 + ((lane & 16) ? 8 : 0);
                ldsm4(a[mi][0], a[mi][1], a[mi][2], a[mi][3], sptr(Ac + arow * 40 + acol));
            }
#pragma unroll
            for (int nj = 0; nj < 3; nj++) {
                int brow = wn * 48 + nj * 16 + (lane & 7) + ((lane & 16) ? 8 : 0);
                int bcol = kk * 16 + ((lane & 8) ? 8 : 0);
                unsigned b0, b1, b2, b3;
                ldsm4(b0, b1, b2, b3, sptr(Bc + brow * 40 + bcol));
#pragma unroll
                for (int mi = 0; mi < 2; mi++) {
                    mma16(acc[mi][nj * 2],     a[mi][0], a[mi][1], a[mi][2], a[mi][3], b0, b1);
                    mma16(acc[mi][nj * 2 + 1], a[mi][0], a[mi][1], a[mi][2], a[mi][3], b2, b3);
                }
            }
        }
    }

#pragma unroll
    for (int mi = 0; mi < 2; mi++)
#pragma unroll
        for (int ni = 0; ni < 6; ni++)
#pragma unroll
            for (int r2 = 0; r2 < 2; r2++) {
                int mrow = mblk + wm * 32 + mi * 16 + g + r2 * 8;
                int n    = nblk + wn * 48 + ni * 8 + tg * 2;
                float v0 = acc[mi][ni][r2 * 2 + 0] + b2[n];
                float v1 = acc[mi][ni][r2 * 2 + 1] + b2[n + 1];
                *(float2*)(out + (size_t)mrow * CDIM + n) = make_float2(v0, v1);
            }
}

// ---------------- launch ----------------
extern "C" void kernel_launch(void* const* d_in, const int* in_sizes, int n_in,
                              void* d_out, int out_size) {
    const float* x     = (const float*)d_in[0];
    const float* mask  = (const float*)d_in[1];
    const float* W1    = (const float*)d_in[2];
    const float* b1    = (const float*)d_in[3];
    const float* W2    = (const float*)d_in[4];
    const float* b2    = (const float*)d_in[5];
    const float* table = (const float*)d_in[6];
    const int*   pidx  = (const int*)d_in[7];

    cudaFuncSetAttribute(k_attn, cudaFuncAttributeMaxDynamicSharedMemorySize, SMEM_ATT);
    cudaFuncSetAttribute(k_qkv,  cudaFuncAttributeMaxDynamicSharedMemorySize, GEMM_SMEM);
    cudaFuncSetAttribute(k_proj, cudaFuncAttributeMaxDynamicSharedMemorySize, GEMM_SMEM);

    k_preh<<<4096, 256>>>(x, W1, W2);
    k_biasq<<<(NW * HEADS * 9 * 2 * 9 * 32 + 255) / 256, 256>>>(table, pidx);
    k_maskq<<<(BTOT * 9 * 2 * 9 * 32 + 255) / 256, 256>>>(mask);
    k_qkv<<<dim3(N1 / 96, M1 / 128), 256, GEMM_SMEM>>>(b1);
    k_attn<<<dim3(HEADS, BTOT), 288, SMEM_ATT>>>();
    k_proj<<<dim3(CDIM / 96, M1 / 128), 256, GEMM_SMEM>>>(b2, (float*)d_out);
}

// round 16
// speedup vs baseline: 1.5144x; 1.0824x over previous
#include <cuda_runtime.h>
#include <cuda_fp16.h>
#include <cstdint>

// ---------------- problem constants (static shapes) ----------------
#define HEADS 6
#define LW    144
#define HD    32
#define CDIM  192
#define NW    64
#define WWINS 15
#define BTOT  960
#define M1    (BTOT*LW)      // 138240
#define N1    576
#define K1    192
#define TABNH (NW*HEADS)

// ---------------- scratch (device globals; no allocations) ----------------
__device__ __half g_xh[(size_t)M1*K1];            // x converted to fp16
__device__ __half g_q[(size_t)BTOT*HEADS*LW*HD];
__device__ __half g_k[(size_t)BTOT*HEADS*LW*HD];
__device__ __half g_v[(size_t)BTOT*HEADS*LW*HD];  // TRANSPOSED: [w][h][d][l]
__device__ __half g_att[(size_t)M1*CDIM];         // fp16 att output
__device__ __half g_w1t[(size_t)N1*K1];           // W1 transposed [n][k] fp16
__device__ __half g_w2t[(size_t)CDIM*CDIM];       // W2 transposed [n][k] fp16
// quad-fragment-ordered bias/mask (fp16): [grp][mt(9)][cb(2)][nt(9)][lane(32)][4]
__device__ __half g_biasQh[(size_t)NW*HEADS*9*2*9*32*4];
__device__ __half g_maskQh[(size_t)BTOT*9*2*9*32*4];

// ---------------- helpers ----------------
__device__ __forceinline__ unsigned pack2h(float lo, float hi) {
    __half2 h = __floats2half2_rn(lo, hi);
    return *reinterpret_cast<unsigned*>(&h);
}

__device__ __forceinline__ void mma16(float c[4],
                                      unsigned a0, unsigned a1, unsigned a2, unsigned a3,
                                      unsigned b0, unsigned b1) {
    asm volatile(
        "mma.sync.aligned.m16n8k16.row.col.f32.f16.f16.f32 "
        "{%0,%1,%2,%3}, {%4,%5,%6,%7}, {%8,%9}, {%0,%1,%2,%3};\n"
        : "+f"(c[0]), "+f"(c[1]), "+f"(c[2]), "+f"(c[3])
        : "r"(a0), "r"(a1), "r"(a2), "r"(a3), "r"(b0), "r"(b1));
}

__device__ __forceinline__ void mma8h(float c[4],
                                      unsigned a0, unsigned a1, unsigned b0) {
    asm volatile(
        "mma.sync.aligned.m16n8k8.row.col.f32.f16.f16.f32 "
        "{%0,%1,%2,%3}, {%4,%5}, {%6}, {%0,%1,%2,%3};\n"
        : "+f"(c[0]), "+f"(c[1]), "+f"(c[2]), "+f"(c[3])
        : "r"(a0), "r"(a1), "r"(b0));
}

__device__ __forceinline__ uint32_t sptr(const void* p) {
    return (uint32_t)__cvta_generic_to_shared(p);
}

__device__ __forceinline__ void ldsm4(unsigned& r0, unsigned& r1, unsigned& r2, unsigned& r3,
                                      uint32_t a) {
    asm volatile("ldmatrix.sync.aligned.m8n8.x4.shared.b16 {%0,%1,%2,%3}, [%4];\n"
                 : "=r"(r0), "=r"(r1), "=r"(r2), "=r"(r3) : "r"(a));
}

__device__ __forceinline__ void ldsm2(unsigned& r0, unsigned& r1, uint32_t a) {
    asm volatile("ldmatrix.sync.aligned.m8n8.x2.shared.b16 {%0,%1}, [%2];\n"
                 : "=r"(r0), "=r"(r1) : "r"(a));
}

__device__ __forceinline__ void cpa16(uint32_t d, const void* s) {
    asm volatile("cp.async.cg.shared.global [%0], [%1], 16;\n" :: "r"(d), "l"(s));
}
__device__ __forceinline__ void cpa_commit() {
    asm volatile("cp.async.commit_group;\n");
}
template <int N> __device__ __forceinline__ void cpa_wait() {
    asm volatile("cp.async.wait_group %0;\n" :: "n"(N));
}

// ---------------- kernel P: convert x to fp16; transpose+convert W1, W2 ----------------
__global__ __launch_bounds__(256) void k_preh(const float* __restrict__ x,
                                              const float* __restrict__ W1,
                                              const float* __restrict__ W2) {
    const size_t i = (size_t)blockIdx.x * 256 + threadIdx.x;
    const size_t stride = (size_t)gridDim.x * 256;
    for (size_t idx = i; idx < (size_t)M1 * K1 / 4; idx += stride) {
        float4 v = *(const float4*)(x + idx * 4);
        unsigned u0 = pack2h(v.x, v.y), u1 = pack2h(v.z, v.w);
        *(uint2*)(g_xh + idx * 4) = make_uint2(u0, u1);
    }
    for (size_t gi = i; gi < (size_t)N1 * K1; gi += stride) {
        int n = (int)(gi / K1), k = (int)(gi % K1);
        g_w1t[gi] = __float2half_rn(W1[(size_t)k * N1 + n]);
    }
    for (size_t gi = i; gi < (size_t)CDIM * CDIM; gi += stride) {
        int n = (int)(gi / CDIM), k = (int)(gi % CDIM);
        g_w2t[gi] = __float2half_rn(W2[(size_t)k * CDIM + n]);
    }
}

// ---------------- kernel B: bias table -> quad-fragment layout (fp16) ----------------
__global__ __launch_bounds__(256) void k_biasq(const float* __restrict__ table,
                                               const int* __restrict__ pidx) {
    int gi = blockIdx.x * 256 + threadIdx.x;
    if (gi >= NW * HEADS * 9 * 2 * 9 * 32) return;
    int lane = gi & 31;
    int nt   = (gi >> 5) % 9;
    int rest = gi / 288;
    int cb   = rest & 1;  rest >>= 1;
    int mt   = rest % 9;  rest /= 9;
    int h    = rest % 6;
    int nw   = rest / 6;
    int r0 = mt * 16 + (lane >> 2);
    int r1 = r0 + 8;
    int c  = cb * 72 + nt * 8 + (lane & 3) * 2;
    int hh = nw * HEADS + h;
    float ox = table[(size_t)pidx[r0 * LW + c]     * TABNH + hh];
    float oy = table[(size_t)pidx[r0 * LW + c + 1] * TABNH + hh];
    float oz = table[(size_t)pidx[r1 * LW + c]     * TABNH + hh];
    float ow = table[(size_t)pidx[r1 * LW + c + 1] * TABNH + hh];
    *(uint2*)(g_biasQh + (size_t)gi * 4) = make_uint2(pack2h(ox, oy), pack2h(oz, ow));
}

// ---------------- kernel M: mask -> quad-fragment layout (fp16) ----------------
__global__ __launch_bounds__(256) void k_maskq(const float* __restrict__ mask) {
    int gi = blockIdx.x * 256 + threadIdx.x;
    if (gi >= BTOT * 9 * 2 * 9 * 32) return;
    int lane = gi & 31;
    int nt   = (gi >> 5) % 9;
    int rest = gi / 288;
    int cb   = rest & 1;  rest >>= 1;
    int mt   = rest % 9;
    int w    = rest / 9;
    int r0 = mt * 16 + (lane >> 2);
    int r1 = r0 + 8;
    int c  = cb * 72 + nt * 8 + (lane & 3) * 2;
    const float* mp = mask + (size_t)w * LW * LW;
    *(uint2*)(g_maskQh + (size_t)gi * 4) =
        make_uint2(pack2h(mp[r0 * LW + c], mp[r0 * LW + c + 1]),
                   pack2h(mp[r1 * LW + c], mp[r1 * LW + c + 1]));
}

// ====== fp16 GEMM: block 128x96, 256 thr (8 warps, 4m x 2n), warp m32 x n48 ======
// k-tile 64 (3 iterations), 2-stage cp.async, 3 CTAs/SM. Strides 72 halves.
#define STG 2
#define A_ST (128 * 72)                          // halves
#define B_ST (96 * 72)
#define GEMM_SMEM (STG * (A_ST + B_ST) * 2)      // 64,512 bytes

// ---------------- kernel 1: QKV = xh @ W1 + b1 (scatter epilogue) ----------------
__global__ __launch_bounds__(256, 3) void k_qkv(const float* __restrict__ b1) {
    extern __shared__ __align__(16) __half smh[];
    __half* As = smh;
    __half* Bs = smh + STG * A_ST;

    const int tid  = threadIdx.x;
    const int lane = tid & 31, wid = tid >> 5;
    const int g = lane >> 2, tg = lane & 3;
    const int wm = wid & 3, wn = wid >> 2;
    const int mblk = blockIdx.y * 128;
    const int nblk = blockIdx.x * 96;

    auto load_stage = [&](int s, int kt) {
        const int k0 = kt * 64;
        __half* Ad = As + s * A_ST;
        __half* Bd = Bs + s * B_ST;
#pragma unroll
        for (int i = 0; i < 4; i++) {               // A: 1024 cp16 (128 x 64h)
            int idx = tid + 256 * i;
            int r = idx >> 3, kc = (idx & 7) << 3;
            cpa16(sptr(Ad + r * 72 + kc), g_xh + (size_t)(mblk + r) * K1 + k0 + kc);
        }
#pragma unroll
        for (int i = 0; i < 3; i++) {               // B: 768 cp16 (96 x 64h, n-major)
            int idx = tid + 256 * i;
            int n = idx >> 3, kc = (idx & 7) << 3;
            cpa16(sptr(Bd + n * 72 + kc), g_w1t + (size_t)(nblk + n) * K1 + k0 + kc);
        }
        cpa_commit();
    };

    load_stage(0, 0);

    float acc[2][6][4];
#pragma unroll
    for (int i = 0; i < 2; i++)
#pragma unroll
        for (int j = 0; j < 6; j++)
#pragma unroll
            for (int r = 0; r < 4; r++) acc[i][j][r] = 0.f;

#pragma unroll 1
    for (int kt = 0; kt < 3; kt++) {
        __syncthreads();
        if (kt < 2) {
            load_stage((kt + 1) & 1, kt + 1);
            cpa_wait<1>();
        } else {
            cpa_wait<0>();
        }
        __syncthreads();

        __half* Ac = As + (kt & 1) * A_ST;
        __half* Bc = Bs + (kt & 1) * B_ST;
#pragma unroll
        for (int kk = 0; kk < 4; kk++) {            // four k16 steps
            unsigned a[2][4];
#pragma unroll
            for (int mi = 0; mi < 2; mi++) {
                int arow = wm * 32 + mi * 16 + (lane & 7) + ((lane & 8) ? 8 : 0);
                int acol = kk * 16 + ((lane & 16) ? 8 : 0);
                ldsm4(a[mi][0], a[mi][1], a[mi][2], a[mi][3], sptr(Ac + arow * 72 + acol));
            }
#pragma unroll
            for (int nj = 0; nj < 3; nj++) {        // three n16 tiles
                int brow = wn * 48 + nj * 16 + (lane & 7) + ((lane & 16) ? 8 : 0);
                int bcol = kk * 16 + ((lane & 8) ? 8 : 0);
                unsigned b0, b1, b2, b3;
                ldsm4(b0, b1, b2, b3, sptr(Bc + brow * 72 + bcol));
#pragma unroll
                for (int mi = 0; mi < 2; mi++) {
                    mma16(acc[mi][nj * 2],     a[mi][0], a[mi][1], a[mi][2], a[mi][3], b0, b1);
                    mma16(acc[mi][nj * 2 + 1], a[mi][0], a[mi][1], a[mi][2], a[mi][3], b2, b3);
                }
            }
        }
    }

    const float SCALE = 0.17677669529663687f;
#pragma unroll
    for (int mi = 0; mi < 2; mi++)
#pragma unroll
        for (int ni = 0; ni < 6; ni++)
#pragma unroll
            for (int r2 = 0; r2 < 2; r2++) {
                int mrow = mblk + wm * 32 + mi * 16 + g + r2 * 8;
                int n    = nblk + wn * 48 + ni * 8 + tg * 2;
                float v0 = acc[mi][ni][r2 * 2 + 0] + b1[n];
                float v1 = acc[mi][ni][r2 * 2 + 1] + b1[n + 1];
                int which = n / 192;
                int nm    = n % 192;
                int head  = nm / 32;
                int d     = nm & 31;
                int win   = mrow / LW;
                int l     = mrow - win * LW;
                if (which == 0) {
                    size_t dst = (((size_t)win * HEADS + head) * LW + l) * HD + d;
                    *reinterpret_cast<__half2*>(g_q + dst) =
                        __floats2half2_rn(v0 * SCALE, v1 * SCALE);
                } else if (which == 1) {
                    size_t dst = (((size_t)win * HEADS + head) * LW + l) * HD + d;
                    *reinterpret_cast<__half2*>(g_k + dst) = __floats2half2_rn(v0, v1);
                } else {
                    size_t baset = ((size_t)win * HEADS + head) * (size_t)(HD * LW);
                    g_v[baset + (size_t)d * LW + l]       = __float2half_rn(v0);
                    g_v[baset + (size_t)(d + 1) * LW + l] = __float2half_rn(v1);
                }
            }
}

// ---------------- kernel 2: FA2 fused attention, fp16 operands + fp16 bias/mask ----------------
// smem (halves): Qs[144][40] + Ks[144][40] + Vt[32][152]  = 32,768 bytes
#define SMEM_ATT ((LW*40 + LW*40 + HD*152) * 2)

__global__ __launch_bounds__(288, 2) void k_attn() {
    extern __shared__ __align__(16) __half smh[];
    __half* Qs = smh;                 // [144][40]
    __half* Ks = Qs + LW * 40;        // [144][40]
    __half* Vt = Ks + LW * 40;        // [32][152]

    const int h = blockIdx.x;
    const int w = blockIdx.y;
    const int nwi = w / WWINS;
    const int tid = threadIdx.x, lane = tid & 31, wid = tid >> 5;   // wid 0..8 (== mt)
    const int g = lane >> 2, tg = lane & 3;

    const size_t base = ((size_t)w * HEADS + h) * LW * HD;
    __half* outp = g_att + (size_t)w * LW * CDIM + h * HD;

    for (int idx = tid; idx < 576; idx += 288) {
        int l = idx >> 2, dc = (idx & 3) << 3;
        *(uint4*)&Qs[l * 40 + dc] = *(const uint4*)(g_q + base + (size_t)idx * 8);
        *(uint4*)&Ks[l * 40 + dc] = *(const uint4*)(g_k + base + (size_t)idx * 8);
        int d = idx / 18, lc = (idx % 18) << 3;
        *(uint4*)&Vt[d * 152 + lc] = *(const uint4*)(g_v + base + (size_t)idx * 8);
    }
    __syncthreads();

    const int m0 = wid * 16;
    unsigned aq[2][4];
    {
        int arow = m0 + (lane & 7) + ((lane & 8) ? 8 : 0);
#pragma unroll
        for (int kk = 0; kk < 2; kk++) {
            int acol = kk * 16 + ((lane & 16) ? 8 : 0);
            ldsm4(aq[kk][0], aq[kk][1], aq[kk][2], aq[kk][3], sptr(Qs + arow * 40 + acol));
        }
    }

    const int r0 = m0 + g, r1 = r0 + 8;
    float mr0 = -1e30f, mr1 = -1e30f;
    float lr0 = 0.f,    lr1 = 0.f;
    float oacc[4][4];
#pragma unroll
    for (int ni = 0; ni < 4; ni++)
#pragma unroll
        for (int r = 0; r < 4; r++) oacc[ni][r] = 0.f;

#pragma unroll
    for (int cb = 0; cb < 2; cb++) {
        const int c0 = cb * 72;
        const uint2* bqc = (const uint2*)g_biasQh
            + ((((size_t)(nwi * HEADS + h) * 9 + wid) * 2 + cb) * 288) + lane;
        const uint2* mqc = (const uint2*)g_maskQh
            + ((((size_t)w * 9 + wid) * 2 + cb) * 288) + lane;

        float sacc[9][4];
#pragma unroll
        for (int nt = 0; nt < 9; nt++)
#pragma unroll
            for (int r = 0; r < 4; r++) sacc[nt][r] = 0.f;

        // --- S = Q K^T (k16 x2 over d=32) ---
#pragma unroll
        for (int kk = 0; kk < 2; kk++) {
#pragma unroll
            for (int ntp = 0; ntp < 4; ntp++) {
                int brow = c0 + ntp * 16 + (lane & 7) + ((lane & 16) ? 8 : 0);
                int bcol = kk * 16 + ((lane & 8) ? 8 : 0);
                unsigned b0, b1, b2, b3;
                ldsm4(b0, b1, b2, b3, sptr(Ks + brow * 40 + bcol));
                mma16(sacc[ntp * 2],     aq[kk][0], aq[kk][1], aq[kk][2], aq[kk][3], b0, b1);
                mma16(sacc[ntp * 2 + 1], aq[kk][0], aq[kk][1], aq[kk][2], aq[kk][3], b2, b3);
            }
            {
                int nrow = c0 + 64 + (lane & 7);
                int ncol = kk * 16 + ((lane & 8) ? 8 : 0);
                unsigned b0, b1;
                ldsm2(b0, b1, sptr(Ks + nrow * 40 + ncol));
                mma16(sacc[8], aq[kk][0], aq[kk][1], aq[kk][2], aq[kk][3], b0, b1);
            }
        }

        // --- + bias + mask (fp16 quad layout, coalesced LDG.64) ---
#pragma unroll
        for (int nt = 0; nt < 9; nt++) {
            uint2 bu = bqc[nt * 32];
            uint2 mu = mqc[nt * 32];
            float2 b01 = __half22float2(*reinterpret_cast<const __half2*>(&bu.x));
            float2 b23 = __half22float2(*reinterpret_cast<const __half2*>(&bu.y));
            float2 m01 = __half22float2(*reinterpret_cast<const __half2*>(&mu.x));
            float2 m23 = __half22float2(*reinterpret_cast<const __half2*>(&mu.y));
            sacc[nt][0] += b01.x + m01.x;
            sacc[nt][1] += b01.y + m01.y;
            sacc[nt][2] += b23.x + m23.x;
            sacc[nt][3] += b23.y + m23.y;
        }

        // --- online softmax ---
        float mx0 = -1e30f, mx1 = -1e30f;
#pragma unroll
        for (int nt = 0; nt < 9; nt++) {
            mx0 = fmaxf(mx0, fmaxf(sacc[nt][0], sacc[nt][1]));
            mx1 = fmaxf(mx1, fmaxf(sacc[nt][2], sacc[nt][3]));
        }
        mx0 = fmaxf(mx0, __shfl_xor_sync(0xffffffffu, mx0, 1));
        mx0 = fmaxf(mx0, __shfl_xor_sync(0xffffffffu, mx0, 2));
        mx1 = fmaxf(mx1, __shfl_xor_sync(0xffffffffu, mx1, 1));
        mx1 = fmaxf(mx1, __shfl_xor_sync(0xffffffffu, mx1, 2));
        const float mn0 = fmaxf(mr0, mx0);
        const float mn1 = fmaxf(mr1, mx1);
        const float sc0 = __expf(mr0 - mn0);
        const float sc1 = __expf(mr1 - mn1);
        mr0 = mn0; mr1 = mn1;

        float sum0 = 0.f, sum1 = 0.f;
#pragma unroll
        for (int nt = 0; nt < 9; nt++) {
            sacc[nt][0] = __expf(sacc[nt][0] - mn0);
            sacc[nt][1] = __expf(sacc[nt][1] - mn0);
            sacc[nt][2] = __expf(sacc[nt][2] - mn1);
            sacc[nt][3] = __expf(sacc[nt][3] - mn1);
            sum0 += sacc[nt][0] + sacc[nt][1];
            sum1 += sacc[nt][2] + sacc[nt][3];
        }
        sum0 += __shfl_xor_sync(0xffffffffu, sum0, 1);
        sum0 += __shfl_xor_sync(0xffffffffu, sum0, 2);
        sum1 += __shfl_xor_sync(0xffffffffu, sum1, 1);
        sum1 += __shfl_xor_sync(0xffffffffu, sum1, 2);
        lr0 = lr0 * sc0 + sum0;
        lr1 = lr1 * sc1 + sum1;

#pragma unroll
        for (int ni = 0; ni < 4; ni++) {
            oacc[ni][0] *= sc0; oacc[ni][1] *= sc0;
            oacc[ni][2] *= sc1; oacc[ni][3] *= sc1;
        }

        // --- O += P V : C-frag == A-frag layout -> pure register packs ---
#pragma unroll
        for (int ks = 0; ks < 4; ks++) {
            unsigned a0 = pack2h(sacc[2*ks][0],     sacc[2*ks][1]);
            unsigned a1 = pack2h(sacc[2*ks][2],     sacc[2*ks][3]);
            unsigned a2 = pack2h(sacc[2*ks + 1][0], sacc[2*ks + 1][1]);
            unsigned a3 = pack2h(sacc[2*ks + 1][2], sacc[2*ks + 1][3]);
            int kcol = c0 + ks * 16 + ((lane & 8) ? 8 : 0);
#pragma unroll
            for (int nip = 0; nip < 2; nip++) {
                int vrow = nip * 16 + (lane & 7) + ((lane & 16) ? 8 : 0);
                unsigned b0, b1, b2, b3;
                ldsm4(b0, b1, b2, b3, sptr(Vt + vrow * 152 + kcol));
                mma16(oacc[nip * 2],     a0, a1, a2, a3, b0, b1);
                mma16(oacc[nip * 2 + 1], a0, a1, a2, a3, b2, b3);
            }
        }
        {                                           // k8 remainder (cols c0+64..71)
            unsigned a0 = pack2h(sacc[8][0], sacc[8][1]);
            unsigned a1 = pack2h(sacc[8][2], sacc[8][3]);
            unsigned b0, b1, b2, b3;
            ldsm4(b0, b1, b2, b3, sptr(Vt + lane * 152 + c0 + 64));
            mma8h(oacc[0], a0, a1, b0);
            mma8h(oacc[1], a0, a1, b1);
            mma8h(oacc[2], a0, a1, b2);
            mma8h(oacc[3], a0, a1, b3);
        }
    }

    const float inv0 = 1.f / lr0;
    const float inv1 = 1.f / lr1;
#pragma unroll
    for (int ni = 0; ni < 4; ni++) {
        int d = ni * 8 + tg * 2;
        *reinterpret_cast<__half2*>(outp + (size_t)r0 * CDIM + d) =
            __floats2half2_rn(oacc[ni][0] * inv0, oacc[ni][1] * inv0);
        *reinterpret_cast<__half2*>(outp + (size_t)r1 * CDIM + d) =
            __floats2half2_rn(oacc[ni][2] * inv1, oacc[ni][3] * inv1);
    }
}

// ---------------- kernel 3: out = att(fp16) @ W2 + b2 (fp32 out) ----------------
__global__ __launch_bounds__(256, 3) void k_proj(const float* __restrict__ b2,
                                                 float* __restrict__ out) {
    extern __shared__ __align__(16) __half smh[];
    __half* As = smh;
    __half* Bs = smh + STG * A_ST;

    const int tid  = threadIdx.x;
    const int lane = tid & 31, wid = tid >> 5;
    const int g = lane >> 2, tg = lane & 3;
    const int wm = wid & 3, wn = wid >> 2;
    const int mblk = blockIdx.y * 128;
    const int nblk = blockIdx.x * 96;

    auto load_stage = [&](int s, int kt) {
        const int k0 = kt * 64;
        __half* Ad = As + s * A_ST;
        __half* Bd = Bs + s * B_ST;
#pragma unroll
        for (int i = 0; i < 4; i++) {
            int idx = tid + 256 * i;
            int r = idx >> 3, kc = (idx & 7) << 3;
            cpa16(sptr(Ad + r * 72 + kc), g_att + (size_t)(mblk + r) * CDIM + k0 + kc);
        }
#pragma unroll
        for (int i = 0; i < 3; i++) {
            int idx = tid + 256 * i;
            int n = idx >> 3, kc = (idx & 7) << 3;
            cpa16(sptr(Bd + n * 72 + kc), g_w2t + (size_t)(nblk + n) * CDIM + k0 + kc);
        }
        cpa_commit();
    };

    load_stage(0, 0);

    float acc[2][6][4];
#pragma unroll
    for (int i = 0; i < 2; i++)
#pragma unroll
        for (int j = 0; j < 6; j++)
#pragma unroll
            for (int r = 0; r < 4; r++) acc[i][j][r] = 0.f;

#pragma unroll 1
    for (int kt = 0; kt < 3; kt++) {
        __syncthreads();
        if (kt < 2) {
            load_stage((kt + 1) & 1, kt + 1);
            cpa_wait<1>();
        } else {
            cpa_wait<0>();
        }
        __syncthreads();

        __half* Ac = As + (kt & 1) * A_ST;
        __half* Bc = Bs + (kt & 1) * B_ST;
#pragma unroll
        for (int kk = 0; kk < 4; kk++) {
            unsigned a[2][4];
#pragma unroll
            for (int mi = 0; mi < 2; mi++) {
                int arow = wm * 32 + mi * 16 + (lane & 7) + ((lane & 8) ? 8 : 0);
                int acol = kk * 16 + ((lane & 16) ? 8 : 0);
                ldsm4(a[mi][0], a[mi][1], a[mi][2], a[mi][3], sptr(Ac + arow * 72 + acol));
            }
#pragma unroll
            for (int nj = 0; nj < 3; nj++) {
                int brow = wn * 48 + nj * 16 + (lane & 7) + ((lane & 16) ? 8 : 0);
                int bcol = kk * 16 + ((lane & 8) ? 8 : 0);
                unsigned b0, b1, b2, b3;
                ldsm4(b0, b1, b2, b3, sptr(Bc + brow * 72 + bcol));
#pragma unroll
                for (int mi = 0; mi < 2; mi++) {
                    mma16(acc[mi][nj * 2],     a[mi][0], a[mi][1], a[mi][2], a[mi][3], b0, b1);
                    mma16(acc[mi][nj * 2 + 1], a[mi][0], a[mi][1], a[mi][2], a[mi][3], b2, b3);
                }
            }
        }
    }

#pragma unroll
    for (int mi = 0; mi < 2; mi++)
#pragma unroll
        for (int ni = 0; ni < 6; ni++)
#pragma unroll
            for (int r2 = 0; r2 < 2; r2++) {
                int mrow = mblk + wm * 32 + mi * 16 + g + r2 * 8;
                int n    = nblk + wn * 48 + ni * 8 + tg * 2;
                float v0 = acc[mi][ni][r2 * 2 + 0] + b2[n];
                float v1 = acc[mi][ni][r2 * 2 + 1] + b2[n + 1];
                *(float2*)(out + (size_t)mrow * CDIM + n) = make_float2(v0, v1);
            }
}

// ---------------- launch ----------------
extern "C" void kernel_launch(void* const* d_in, const int* in_sizes, int n_in,
                              void* d_out, int out_size) {
    const float* x     = (const float*)d_in[0];
    const float* mask  = (const float*)d_in[1];
    const float* W1    = (const float*)d_in[2];
    const float* b1    = (const float*)d_in[3];
    const float* W2    = (const float*)d_in[4];
    const float* b2    = (const float*)d_in[5];
    const float* table = (const float*)d_in[6];
    const int*   pidx  = (const int*)d_in[7];

    cudaFuncSetAttribute(k_attn, cudaFuncAttributeMaxDynamicSharedMemorySize, SMEM_ATT);
    cudaFuncSetAttribute(k_qkv,  cudaFuncAttributeMaxDynamicSharedMemorySize, GEMM_SMEM);
    cudaFuncSetAttribute(k_proj, cudaFuncAttributeMaxDynamicSharedMemorySize, GEMM_SMEM);

    k_preh<<<4096, 256>>>(x, W1, W2);
    k_biasq<<<(NW * HEADS * 9 * 2 * 9 * 32 + 255) / 256, 256>>>(table, pidx);
    k_maskq<<<(BTOT * 9 * 2 * 9 * 32 + 255) / 256, 256>>>(mask);
    k_qkv<<<dim3(N1 / 96, M1 / 128), 256, GEMM_SMEM>>>(b1);
    k_attn<<<dim3(HEADS, BTOT), 288, SMEM_ATT>>>();
    k_proj<<<dim3(CDIM / 96, M1 / 128), 256, GEMM_SMEM>>>(b2, (float*)d_out);
}